// round 13
// baseline (speedup 1.0000x reference)
#include <cuda_runtime.h>

#define BATCH 64
#define NTOK  197
#define DIMC  768
#define NHEAD 8
#define HDIM  96
#define NROWS (BATCH*NTOK)     // 12608
#define HIDC  3072
#define NBIAS 841
#define A2STR 224              // padded m-stride for A2 (7 * 32)

// ---------------- scratch (device globals; no allocations) ----------------
__device__ float g_h  [(size_t)NROWS*DIMC];                 // LN1 out, reused for LN2 out
__device__ float g_qkv[(size_t)NROWS*3*DIMC];               // qkv, q/k normalized in place
__device__ float g_S  [(size_t)BATCH*NHEAD*NTOK*NTOK];      // raw q.k logits
__device__ float g_A2 [(size_t)BATCH*NHEAD*NTOK*A2STR];     // post-mixed attention probs (padded)
__device__ float g_att[(size_t)NROWS*DIMC];                 // attention output (b,n,h*d)
__device__ float g_x1 [(size_t)NROWS*DIMC];                 // x + proj(out)
__device__ float g_hid[(size_t)NROWS*HIDC];                 // MLP hidden
__device__ float g_rpb[(size_t)NBIAS*NHEAD];                // position-bias table

// ---------------- helpers ----------------
__device__ __forceinline__ float block_sum256(float v) {
    __shared__ float red[8];
    #pragma unroll
    for (int o = 16; o; o >>= 1) v += __shfl_xor_sync(0xffffffffu, v, o);
    __syncthreads();                       // protect red across calls
    if ((threadIdx.x & 31) == 0) red[threadIdx.x >> 5] = v;
    __syncthreads();
    float s = 0.f;
    #pragma unroll
    for (int i = 0; i < 8; i++) s += red[i];
    return s;
}

// ---------------- LayerNorm (row = 768, 256 threads/row) ----------------
__global__ void __launch_bounds__(256) ln_kernel(const float* __restrict__ x,
                                                 const float* __restrict__ w,
                                                 const float* __restrict__ b,
                                                 float* __restrict__ out) {
    size_t row = blockIdx.x;
    const float* xr = x + row * DIMC;
    int t = threadIdx.x;
    float v0 = xr[t], v1 = xr[t + 256], v2 = xr[t + 512];
    float mean = block_sum256(v0 + v1 + v2) * (1.0f / DIMC);
    float d0 = v0 - mean, d1 = v1 - mean, d2 = v2 - mean;
    float var = block_sum256(d0*d0 + d1*d1 + d2*d2) * (1.0f / DIMC);
    float rstd = rsqrtf(var + 1e-5f);
    float* o = out + row * DIMC;
    o[t]       = d0 * rstd * w[t]       + b[t];
    o[t + 256] = d1 * rstd * w[t + 256] + b[t + 256];
    o[t + 512] = d2 * rstd * w[t + 512] + b[t + 512];
}

// ---------------- generic tiled SGEMM: C = A(M,K) * B(N,K)^T ----------------
// BM=64, BN=128, BK=16, 256 threads, 4x8 microtile. M=12608 (=64*197) exact,
// N in {768,2304,3072} (=128*k) exact, K in {768,3072} (=16*k) exact.
template<bool HASB, bool HASR, bool GELU>
__global__ void __launch_bounds__(256) sgemm_kernel(const float* __restrict__ A,
                                                    const float* __restrict__ Bw,
                                                    const float* __restrict__ bias,
                                                    const float* __restrict__ res,
                                                    float* __restrict__ C,
                                                    int K, int N) {
    __shared__ float As[16 * 68];
    __shared__ float Bs[16 * 132];
    int tid = threadIdx.x;
    int ty = tid >> 4, tx = tid & 15;
    const float* Ab = A  + (size_t)(blockIdx.y * 64)  * K;
    const float* Bb = Bw + (size_t)(blockIdx.x * 128) * K;
    float acc[4][8];
    #pragma unroll
    for (int i = 0; i < 4; i++)
        #pragma unroll
        for (int j = 0; j < 8; j++) acc[i][j] = 0.f;

    int lr = tid >> 2;          // 0..63
    int lk = (tid & 3) << 2;    // 0,4,8,12

    for (int k0 = 0; k0 < K; k0 += 16) {
        float4 a4 = *(const float4*)(Ab + (size_t)lr * K + k0 + lk);
        As[(lk+0)*68 + lr] = a4.x; As[(lk+1)*68 + lr] = a4.y;
        As[(lk+2)*68 + lr] = a4.z; As[(lk+3)*68 + lr] = a4.w;
        #pragma unroll
        for (int it = 0; it < 2; it++) {
            int br = lr + it * 64;
            float4 b4 = *(const float4*)(Bb + (size_t)br * K + k0 + lk);
            Bs[(lk+0)*132 + br] = b4.x; Bs[(lk+1)*132 + br] = b4.y;
            Bs[(lk+2)*132 + br] = b4.z; Bs[(lk+3)*132 + br] = b4.w;
        }
        __syncthreads();
        #pragma unroll
        for (int k = 0; k < 16; k++) {
            float4 av = *(const float4*)&As[k*68  + ty*4];
            float4 b0 = *(const float4*)&Bs[k*132 + tx*8];
            float4 b1 = *(const float4*)&Bs[k*132 + tx*8 + 4];
            float aa[4] = {av.x, av.y, av.z, av.w};
            float bb[8] = {b0.x, b0.y, b0.z, b0.w, b1.x, b1.y, b1.z, b1.w};
            #pragma unroll
            for (int i = 0; i < 4; i++)
                #pragma unroll
                for (int j = 0; j < 8; j++) acc[i][j] += aa[i] * bb[j];
        }
        __syncthreads();
    }

    int row0 = blockIdx.y * 64  + ty * 4;
    int col0 = blockIdx.x * 128 + tx * 8;
    #pragma unroll
    for (int i = 0; i < 4; i++) {
        size_t rbase = (size_t)(row0 + i) * N + col0;
        #pragma unroll
        for (int j = 0; j < 8; j++) {
            float vv = acc[i][j];
            if (HASB) vv += bias[col0 + j];
            if (GELU) vv = vv * normcdff(vv);   // exact gelu: x * Phi(x)
            if (HASR) vv += res[rbase + j];
            C[rbase + j] = vv;
        }
    }
}

// ---------------- l2-normalize q and k per (b,h,n), fold scale into q ----------------
__global__ void __launch_bounds__(256) l2norm_kernel(float* __restrict__ qkv,
                                                     const float* __restrict__ scale) {
    int warp = (blockIdx.x * 256 + threadIdx.x) >> 5;
    int lane = threadIdx.x & 31;
    // warp id -> (bn, h, part)
    int p  = warp & 1;
    int h  = (warp >> 1) & 7;
    int bn = warp >> 4;
    float* v = qkv + (size_t)bn * 3 * DIMC + p * DIMC + h * HDIM;
    float a0 = v[lane], a1 = v[lane + 32], a2 = v[lane + 64];
    float ss = a0*a0 + a1*a1 + a2*a2;
    #pragma unroll
    for (int o = 16; o; o >>= 1) ss += __shfl_xor_sync(0xffffffffu, ss, o);
    float inv = 1.0f / fmaxf(sqrtf(ss), 1e-12f);
    if (p == 0) inv *= fminf(scale[h], 100.0f);
    v[lane]      = a0 * inv;
    v[lane + 32] = a1 * inv;
    v[lane + 64] = a2 * inv;
}

// ---------------- dynamic position-bias MLP (841 rows) ----------------
__device__ __forceinline__ void pos_stage(float* p, const float* lnw, const float* lnb,
                                          const float* fcw, const float* fcb, int outdim,
                                          float* v, float* stat, float* outp) {
    int t = threadIdx.x;
    if (t == 0) {
        float m = 0.f;
        for (int i = 0; i < 48; i++) m += p[i];
        m *= (1.0f / 48.0f);
        float var = 0.f;
        for (int i = 0; i < 48; i++) { float d = p[i] - m; var += d * d; }
        var *= (1.0f / 48.0f);
        stat[0] = m; stat[1] = rsqrtf(var + 1e-5f);
    }
    __syncthreads();
    if (t < 48) v[t] = fmaxf((p[t] - stat[0]) * stat[1] * lnw[t] + lnb[t], 0.f);
    __syncthreads();
    float s = 0.f;
    if (t < outdim) {
        s = fcb[t];
        for (int i = 0; i < 48; i++) s += fcw[t * 48 + i] * v[i];
    }
    __syncthreads();
    if (t < outdim) outp[t] = s;
    __syncthreads();
}

__global__ void __launch_bounds__(64) posmlp_kernel(
    const float* __restrict__ biases, const float* __restrict__ ppw, const float* __restrict__ ppb,
    const float* __restrict__ l1w, const float* __restrict__ l1b,
    const float* __restrict__ f1w, const float* __restrict__ f1b,
    const float* __restrict__ l2w, const float* __restrict__ l2b,
    const float* __restrict__ f2w, const float* __restrict__ f2b,
    const float* __restrict__ l3w, const float* __restrict__ l3b,
    const float* __restrict__ f3w, const float* __restrict__ f3b,
    float* __restrict__ rpb) {
    __shared__ float p[48], v[48], stat[2];
    int r = blockIdx.x, t = threadIdx.x;
    if (t < 48) p[t] = biases[r*2] * ppw[t*2] + biases[r*2+1] * ppw[t*2+1] + ppb[t];
    __syncthreads();
    pos_stage(p, l1w, l1b, f1w, f1b, 48, v, stat, p);
    pos_stage(p, l2w, l2b, f2w, f2b, 48, v, stat, p);
    pos_stage(p, l3w, l3b, f3w, f3b, NHEAD, v, stat, rpb + (size_t)r * NHEAD);
}

// ---------------- S = qn . kn^T per (b,h); 64x64 tile, K=96 ----------------
__global__ void __launch_bounds__(256) qk_kernel(const float* __restrict__ qkv,
                                                 float* __restrict__ S) {
    int bh = blockIdx.z; int b = bh >> 3, h = bh & 7;
    int n0 = blockIdx.y * 64, m0 = blockIdx.x * 64;
    __shared__ float Qs[32 * 68];
    __shared__ float Ks[32 * 68];
    int tid = threadIdx.x, ty = tid >> 4, tx = tid & 15;
    float acc[4][4];
    #pragma unroll
    for (int i = 0; i < 4; i++)
        #pragma unroll
        for (int j = 0; j < 4; j++) acc[i][j] = 0.f;

    const float* qb = qkv + (size_t)b * NTOK * 3 * DIMC + h * HDIM;
    const float* kb = qb + DIMC;

    for (int kt = 0; kt < HDIM; kt += 32) {
        #pragma unroll
        for (int it = 0; it < 2; it++) {
            int li = tid + it * 256;
            int row = li >> 3, c4 = (li & 7) << 2;
            float4 qv = {0,0,0,0}, kv = {0,0,0,0};
            int n = n0 + row, m = m0 + row;
            if (n < NTOK) qv = *(const float4*)(qb + (size_t)n * 3 * DIMC + kt + c4);
            if (m < NTOK) kv = *(const float4*)(kb + (size_t)m * 3 * DIMC + kt + c4);
            Qs[(c4+0)*68 + row] = qv.x; Qs[(c4+1)*68 + row] = qv.y;
            Qs[(c4+2)*68 + row] = qv.z; Qs[(c4+3)*68 + row] = qv.w;
            Ks[(c4+0)*68 + row] = kv.x; Ks[(c4+1)*68 + row] = kv.y;
            Ks[(c4+2)*68 + row] = kv.z; Ks[(c4+3)*68 + row] = kv.w;
        }
        __syncthreads();
        #pragma unroll
        for (int k = 0; k < 32; k++) {
            float4 a = *(const float4*)&Qs[k*68 + ty*4];
            float4 c = *(const float4*)&Ks[k*68 + tx*4];
            float aa[4] = {a.x, a.y, a.z, a.w};
            float cc[4] = {c.x, c.y, c.z, c.w};
            #pragma unroll
            for (int i = 0; i < 4; i++)
                #pragma unroll
                for (int j = 0; j < 4; j++) acc[i][j] += aa[i] * cc[j];
        }
        __syncthreads();
    }
    #pragma unroll
    for (int i = 0; i < 4; i++) {
        int n = n0 + ty*4 + i; if (n >= NTOK) continue;
        #pragma unroll
        for (int j = 0; j < 4; j++) {
            int m = m0 + tx*4 + j; if (m >= NTOK) continue;
            S[((size_t)bh * NTOK + n) * NTOK + m] = acc[i][j];
        }
    }
}

// ---------------- +rpb, pre-mix, mask, softmax, post-mix (per (b,n)) ----------------
__global__ void __launch_bounds__(256) mixsoft_kernel(const float* __restrict__ S,
                                                      const float* __restrict__ rpb,
                                                      const int* __restrict__ rel_idx,
                                                      const float* __restrict__ pre_w,
                                                      const float* __restrict__ post_w,
                                                      const float* __restrict__ adj,
                                                      float* __restrict__ A2) {
    int bn = blockIdx.x;
    int b = bn / NTOK, n = bn - b * NTOK;
    __shared__ float L [8 * 200];
    __shared__ float Mx[8 * 200];
    __shared__ int   rel[NTOK];
    __shared__ float prew[64], postw[64];
    int tid = threadIdx.x;
    if (tid < 64) { prew[tid] = pre_w[tid]; postw[tid] = post_w[tid]; }
    if (tid < NTOK) rel[tid] = rel_idx[(size_t)n * NTOK + tid];
    __syncthreads();

    for (int idx = tid; idx < 8 * NTOK; idx += 256) {
        int h = idx / NTOK, m = idx - h * NTOK;
        L[h*200 + m] = S[((size_t)(b*8 + h) * NTOK + n) * NTOK + m]
                       + rpb[(size_t)rel[m] * NHEAD + h];
    }
    __syncthreads();

    for (int idx = tid; idx < 8 * NTOK; idx += 256) {
        int o = idx / NTOK, m = idx - o * NTOK;
        float s = 0.f;
        #pragma unroll
        for (int h = 0; h < 8; h++) s += prew[o*8 + h] * L[h*200 + m];
        float a = adj[((size_t)o * NTOK + n) * NTOK + m];
        Mx[o*200 + m] = (a > 0.f) ? s : -1e9f;
    }
    __syncthreads();

    // softmax: warp w handles row o = w
    int w = tid >> 5, lane = tid & 31;
    float mxv = -3.0e38f;
    for (int m = lane; m < NTOK; m += 32) mxv = fmaxf(mxv, Mx[w*200 + m]);
    #pragma unroll
    for (int o = 16; o; o >>= 1) mxv = fmaxf(mxv, __shfl_xor_sync(0xffffffffu, mxv, o));
    float sum = 0.f;
    for (int m = lane; m < NTOK; m += 32) {
        float e = expf(Mx[w*200 + m] - mxv);
        Mx[w*200 + m] = e;
        sum += e;
    }
    #pragma unroll
    for (int o = 16; o; o >>= 1) sum += __shfl_xor_sync(0xffffffffu, sum, o);
    float inv = 1.0f / sum;
    for (int m = lane; m < NTOK; m += 32) Mx[w*200 + m] *= inv;
    __syncthreads();

    for (int idx = tid; idx < 8 * A2STR; idx += 256) {
        int o = idx / A2STR, m = idx - o * A2STR;
        float s = 0.f;
        if (m < NTOK) {
            #pragma unroll
            for (int h = 0; h < 8; h++) s += postw[o*8 + h] * Mx[h*200 + m];
        }
        A2[((size_t)(b*8 + o) * NTOK + n) * A2STR + m] = s;  // zero-filled padding
    }
}

// ---------------- out = A2 . V per (b,h); 64n x 96d tile ----------------
__global__ void __launch_bounds__(256) av_kernel(const float* __restrict__ A2,
                                                 const float* __restrict__ qkv,
                                                 float* __restrict__ out) {
    int bh = blockIdx.y; int b = bh >> 3, h = bh & 7;
    int n0 = blockIdx.x * 64;
    __shared__ float As[32 * 68];
    __shared__ float Vs[32 * 100];
    int tid = threadIdx.x, ty = tid >> 4, tx = tid & 15;
    float acc[4][6];
    #pragma unroll
    for (int i = 0; i < 4; i++)
        #pragma unroll
        for (int j = 0; j < 6; j++) acc[i][j] = 0.f;

    const float* A2b = A2 + (size_t)bh * NTOK * A2STR;
    const float* vb  = qkv + (size_t)b * NTOK * 3 * DIMC + 2 * DIMC + h * HDIM;

    for (int m0 = 0; m0 < A2STR; m0 += 32) {
        #pragma unroll
        for (int it = 0; it < 2; it++) {
            int li = tid + it * 256;
            int row = li >> 3, c4 = (li & 7) << 2;
            int n = n0 + row;
            float4 a4 = {0,0,0,0};
            if (n < NTOK) a4 = *(const float4*)(A2b + (size_t)n * A2STR + m0 + c4);
            As[(c4+0)*68 + row] = a4.x; As[(c4+1)*68 + row] = a4.y;
            As[(c4+2)*68 + row] = a4.z; As[(c4+3)*68 + row] = a4.w;
        }
        #pragma unroll
        for (int it = 0; it < 3; it++) {
            int li = tid + it * 256;
            int row = li / 24, c4 = (li - row * 24) * 4;
            int m = m0 + row;
            float4 v4 = {0,0,0,0};
            if (m < NTOK) v4 = *(const float4*)(vb + (size_t)m * 3 * DIMC + c4);
            *(float4*)&Vs[row*100 + c4] = v4;
        }
        __syncthreads();
        #pragma unroll
        for (int k = 0; k < 32; k++) {
            float4 a = *(const float4*)&As[k*68 + ty*4];
            float aa[4] = {a.x, a.y, a.z, a.w};
            float bb[6];
            #pragma unroll
            for (int j = 0; j < 6; j++) bb[j] = Vs[k*100 + tx*6 + j];
            #pragma unroll
            for (int i = 0; i < 4; i++)
                #pragma unroll
                for (int j = 0; j < 6; j++) acc[i][j] += aa[i] * bb[j];
        }
        __syncthreads();
    }
    #pragma unroll
    for (int i = 0; i < 4; i++) {
        int n = n0 + ty*4 + i; if (n >= NTOK) continue;
        float* op = out + ((size_t)b * NTOK + n) * DIMC + h * HDIM + tx * 6;
        #pragma unroll
        for (int j = 0; j < 6; j++) op[j] = acc[i][j];
    }
}

// ---------------- host launcher ----------------
extern "C" void kernel_launch(void* const* d_in, const int* in_sizes, int n_in,
                              void* d_out, int out_size) {
    const float* x        = (const float*)d_in[0];
    const float* norm1_w  = (const float*)d_in[1];
    const float* norm1_b  = (const float*)d_in[2];
    const float* qkv_w    = (const float*)d_in[3];
    const float* scale    = (const float*)d_in[4];
    const float* pp_w     = (const float*)d_in[5];
    const float* pp_b     = (const float*)d_in[6];
    const float* ln1_w    = (const float*)d_in[7];
    const float* ln1_b    = (const float*)d_in[8];
    const float* fcp1_w   = (const float*)d_in[9];
    const float* fcp1_b   = (const float*)d_in[10];
    const float* ln2_w    = (const float*)d_in[11];
    const float* ln2_b    = (const float*)d_in[12];
    const float* fcp2_w   = (const float*)d_in[13];
    const float* fcp2_b   = (const float*)d_in[14];
    const float* ln3_w    = (const float*)d_in[15];
    const float* ln3_b    = (const float*)d_in[16];
    const float* fcp3_w   = (const float*)d_in[17];
    const float* fcp3_b   = (const float*)d_in[18];
    const float* pre_w    = (const float*)d_in[19];
    const float* post_w   = (const float*)d_in[20];
    const float* proj_w   = (const float*)d_in[21];
    const float* proj_b   = (const float*)d_in[22];
    const float* norm2_w  = (const float*)d_in[23];
    const float* norm2_b  = (const float*)d_in[24];
    const float* m1_w     = (const float*)d_in[25];
    const float* m1_b     = (const float*)d_in[26];
    const float* m2_w     = (const float*)d_in[27];
    const float* m2_b     = (const float*)d_in[28];
    const float* prior    = (const float*)d_in[29];
    const float* biases   = (const float*)d_in[30];
    const int*   rel_idx  = (const int*)  d_in[31];

    float *ph, *pqkv, *pS, *pA2, *patt, *px1, *phid, *prpb;
    cudaGetSymbolAddress((void**)&ph,   g_h);
    cudaGetSymbolAddress((void**)&pqkv, g_qkv);
    cudaGetSymbolAddress((void**)&pS,   g_S);
    cudaGetSymbolAddress((void**)&pA2,  g_A2);
    cudaGetSymbolAddress((void**)&patt, g_att);
    cudaGetSymbolAddress((void**)&px1,  g_x1);
    cudaGetSymbolAddress((void**)&phid, g_hid);
    cudaGetSymbolAddress((void**)&prpb, g_rpb);

    // 1. LN1
    ln_kernel<<<NROWS, 256>>>(x, norm1_w, norm1_b, ph);
    // 2. QKV GEMM (no bias)
    sgemm_kernel<false, false, false><<<dim3(3*DIMC/128, NROWS/64), 256>>>(
        ph, qkv_w, nullptr, nullptr, pqkv, DIMC, 3*DIMC);
    // 3. l2-normalize q,k (scale folded into q)
    l2norm_kernel<<<(NROWS * NHEAD * 2) / 8, 256>>>(pqkv, scale);
    // 4. position-bias MLP
    posmlp_kernel<<<NBIAS, 64>>>(biases, pp_w, pp_b,
                                 ln1_w, ln1_b, fcp1_w, fcp1_b,
                                 ln2_w, ln2_b, fcp2_w, fcp2_b,
                                 ln3_w, ln3_b, fcp3_w, fcp3_b, prpb);
    // 5. S = qn . kn^T
    qk_kernel<<<dim3(4, 4, BATCH*NHEAD), 256>>>(pqkv, pS);
    // 6. +rpb, pre-mix, mask, softmax, post-mix
    mixsoft_kernel<<<NROWS, 256>>>(pS, prpb, rel_idx, pre_w, post_w, prior, pA2);
    // 7. out = A2 . V  -> (b,n,h*d)
    av_kernel<<<dim3(4, BATCH*NHEAD), 256>>>(pA2, pqkv, patt);
    // 8. proj + bias + residual x -> x1
    sgemm_kernel<true, true, false><<<dim3(DIMC/128, NROWS/64), 256>>>(
        patt, proj_w, proj_b, x, px1, DIMC, DIMC);
    // 9. LN2
    ln_kernel<<<NROWS, 256>>>(px1, norm2_w, norm2_b, ph);
    // 10. MLP fc1 + gelu
    sgemm_kernel<true, false, true><<<dim3(HIDC/128, NROWS/64), 256>>>(
        ph, m1_w, m1_b, nullptr, phid, DIMC, HIDC);
    // 11. MLP fc2 + bias + residual x1 -> out
    sgemm_kernel<true, true, false><<<dim3(DIMC/128, NROWS/64), 256>>>(
        phid, m2_w, m2_b, px1, (float*)d_out, HIDC, DIMC);
}